// round 6
// baseline (speedup 1.0000x reference)
#include <cuda_runtime.h>

#define NG     2048
#define WIMG   128
#define KTOP   10
#define TILE   8
#define TPD    16
#define NTILES 256
#define SPLIT  8
#define CAP    768

typedef unsigned long long u64;

// ---- scratch (__device__ globals; no allocations) ----
__device__ float4 d_P4[NG];            // (-mean_x, -mean_y, a', b')  [-0.5*log2e folded]
__device__ float  d_PC[NG];            // c'
__device__ float4 d_C4[NG];            // (r, g, b, 0)
__device__ int    d_list[NTILES * NG]; // per-tile gaussian index lists (ascending g)
__device__ int    d_cnt[NTILES];

// One block per tile. Bitmask cull + warp-scan ordered compaction (3 syncs).
// Blocks 0..7 also compute per-gaussian quadratic params (one g per thread).
__global__ void __launch_bounds__(256) bin_prep_kernel(
    const float* __restrict__ means, const float* __restrict__ rots,
    const float* __restrict__ lsc,   const float* __restrict__ cols) {
    __shared__ unsigned s_hw[64];   // hit bits: word w bit b <-> gaussian 32w+b
    __shared__ int      s_gb[32];   // exclusive base per 64-gaussian group

    const int tile = blockIdx.x;
    const int t    = threadIdx.x;
    const float x0 = (float)((tile & 15) * TILE) + 0.5f;
    const float y0 = (float)((tile >> 4) * TILE) + 0.5f;
    const float x1 = x0 + 7.0f, y1 = y0 + 7.0f;

    // ---- param writes (blocks 0..7 only; g = blockIdx.x*256 + t) ----
    if (blockIdx.x < 8) {
        int g = blockIdx.x * 256 + t;
        float th = rots[g];
        float ct = cosf(th), st = sinf(th);
        float ivx = expf(-2.0f * lsc[2*g + 0]);
        float ivy = expf(-2.0f * lsc[2*g + 1]);
        float a = ct*ct*ivx + st*st*ivy;
        float c = st*st*ivx + ct*ct*ivy;
        float b = ct*st*(ivx - ivy);
        const float L = 1.4426950408889634f;   // log2(e)
        // alpha = 2^(a' dx^2 + b' dx dy + c' dy^2)
        d_P4[g] = make_float4(-means[2*g + 0], -means[2*g + 1], -0.5f*L*a, -L*b);
        d_PC[g] = -0.5f * L * c;
        d_C4[g] = make_float4(cols[3*g + 0], cols[3*g + 1], cols[3*g + 2], 0.0f);
    }

    // ---- hit tests: thread t covers gaussians [8t, 8t+8), vectorized ----
    const float4* m4 = (const float4*)means;  // 2 gaussians per float4
    const float4* l4 = (const float4*)lsc;
    unsigned mask = 0;
#pragma unroll
    for (int j = 0; j < 4; j++) {
        float4 mm = m4[4*t + j];
        float4 ll = l4[4*t + j];
        // alpha >= ~8e-9 requires |d| <= 6.1*sigma_max
        float r = 6.1f * __expf(fmaxf(ll.x, ll.y));
        float cdx = fmaxf(fmaxf(x0 - mm.x, mm.x - x1), 0.0f);
        float cdy = fmaxf(fmaxf(y0 - mm.y, mm.y - y1), 0.0f);
        if (cdx*cdx + cdy*cdy <= r*r) mask |= 1u << (2*j);
        r = 6.1f * __expf(fmaxf(ll.z, ll.w));
        cdx = fmaxf(fmaxf(x0 - mm.z, mm.z - x1), 0.0f);
        cdy = fmaxf(fmaxf(y0 - mm.w, mm.w - y1), 0.0f);
        if (cdx*cdx + cdy*cdy <= r*r) mask |= 1u << (2*j + 1);
    }
    ((unsigned char*)s_hw)[t] = (unsigned char)mask;  // byte t&3 of word t>>2
    __syncthreads();

    // ---- warp 0: inclusive shfl-scan of popcounts over 64-gaussian groups ----
    if (t < 32) {
        int c = __popc(s_hw[2*t]) + __popc(s_hw[2*t + 1]);
        int inc = c;
#pragma unroll
        for (int d = 1; d < 32; d <<= 1) {
            int n = __shfl_up_sync(0xffffffffu, inc, d);
            if (t >= d) inc += n;
        }
        s_gb[t] = inc - c;
        if (t == 31) d_cnt[tile] = inc;
    }
    __syncthreads();

    // ---- ordered scatter ----
    {
        int grp = t >> 3;                       // 64-gaussian group
        unsigned w0 = s_hw[2*grp], w1 = s_hw[2*grp + 1];
        int bidx = t & 7;                       // byte index within group
        int pre;
        if (bidx < 4) pre = __popc(w0 & ((1u << (8*bidx)) - 1u));
        else          pre = __popc(w0) + __popc(w1 & ((1u << (8*(bidx-4))) - 1u));
        int pos = s_gb[grp] + pre;
        int* lst = d_list + tile * NG;
#pragma unroll
        for (int j = 0; j < 8; j++)
            if (mask & (1u << j)) lst[pos++] = 8*t + j;
    }
}

__device__ __forceinline__ float ex2f(float x) {
    float y;
    asm("ex2.approx.ftz.f32 %0, %1;" : "=f"(y) : "f"(x));
    return y;
}

// Block = half-tile (32 px) x SPLIT(8) = 256 threads, grid = 512.
// Params staged in shared; 64-bit keys (full alpha bits << 11 | (2047-g)) give
// exact alpha ordering with top_k's smallest-index tie-break in one compare.
__global__ void __launch_bounds__(256) render_kernel(float* __restrict__ out) {
    __shared__ float4 s_p4[CAP];
    __shared__ float2 s_pcg[CAP];                 // (c', g as int-bits)
    __shared__ u64    s_key[32][SPLIT * KTOP + 1]; // stride 81 (odd) -> clean

    const int tid  = threadIdx.x;
    const int lane = tid & 31;      // pixel within half-tile
    const int sp   = tid >> 5;      // split id 0..7
    const int tb   = blockIdx.x >> 1;
    const int half = blockIdx.x & 1;
    const int tx = tb & (TPD-1), ty = tb >> 4;
    const int pit = half * 32 + lane;        // pixel-in-tile 0..63
    const int pxi = pit & (TILE-1), pyi = pit >> 3;
    const float px = (float)(tx * TILE + pxi) + 0.5f;
    const float py = (float)(ty * TILE + pyi) + 0.5f;

    const int len = d_cnt[tb];
    const int* __restrict__ lst = d_list + tb * NG;

    // stage list params into shared (once per block)
    const int lim = len < CAP ? len : CAP;
    for (int i = tid; i < lim; i += 256) {
        int g = lst[i];
        s_p4[i]  = d_P4[g];
        s_pcg[i] = make_float2(d_PC[g], __int_as_float(g));
    }
    __syncthreads();

    const int chunk = (len + SPLIT - 1) / SPLIT;
    const int s = sp * chunk;
    const int e = min(s + chunk, len);

    u64 kq[KTOP];
#pragma unroll
    for (int k = 0; k < KTOP; k++) kq[k] = 0ull;

#pragma unroll 2
    for (int i = s; i < e; i++) {
        float4 p; float cc; int g;
        if (i < CAP) {
            p = s_p4[i];
            float2 pcg = s_pcg[i];
            cc = pcg.x; g = __float_as_int(pcg.y);
        } else {
            g = __ldg(lst + i); p = d_P4[g]; cc = d_PC[g];
        }
        float dx = px + p.x;
        float dy = py + p.y;
        float t1 = fmaf(p.w, dy, p.z * dx);
        float q  = fmaf(dx, t1, (cc * dy) * dy);
        float alpha = ex2f(q);
        unsigned abits = __float_as_uint(alpha);   // alpha>0 -> monotone as u32
        u64 key = ((u64)abits << 11) | (u64)(2047 - g);
        if (key > kq[KTOP - 1]) {
            u64 v = key;
#pragma unroll
            for (int k = 0; k < KTOP; k++) {
                bool tk = v > kq[k];
                u64 hi = tk ? v : kq[k];
                u64 lo = tk ? kq[k] : v;
                kq[k] = hi; v = lo;
            }
        }
    }

#pragma unroll
    for (int k = 0; k < KTOP; k++) s_key[lane][sp * KTOP + k] = kq[k];
    __syncthreads();

    if (tid < 32) {
        int h0=0,h1=0,h2=0,h3=0,h4=0,h5=0,h6=0,h7=0;
        float T = 1.0f, rr = 0.0f, gg = 0.0f, bb = 0.0f;
#pragma unroll
        for (int k = 0; k < KTOP; k++) {
            u64 best = s_key[lane][0*KTOP + h0]; int bs = 0;
            u64 v;
            v = s_key[lane][1*KTOP + h1]; if (v > best) { best = v; bs = 1; }
            v = s_key[lane][2*KTOP + h2]; if (v > best) { best = v; bs = 2; }
            v = s_key[lane][3*KTOP + h3]; if (v > best) { best = v; bs = 3; }
            v = s_key[lane][4*KTOP + h4]; if (v > best) { best = v; bs = 4; }
            v = s_key[lane][5*KTOP + h5]; if (v > best) { best = v; bs = 5; }
            v = s_key[lane][6*KTOP + h6]; if (v > best) { best = v; bs = 6; }
            v = s_key[lane][7*KTOP + h7]; if (v > best) { best = v; bs = 7; }
            h0 += (bs==0); h1 += (bs==1); h2 += (bs==2); h3 += (bs==3);
            h4 += (bs==4); h5 += (bs==5); h6 += (bs==6); h7 += (bs==7);

            int g = 2047 - (int)(best & 2047ull);
            float alpha = __uint_as_float((unsigned)(best >> 11));
            float4 col = d_C4[g];
            float wgt = alpha * T;
            rr = fmaf(wgt, col.x, rr);
            gg = fmaf(wgt, col.y, gg);
            bb = fmaf(wgt, col.z, bb);
            T *= (1.0f - alpha);
        }
        int pix = (ty * TILE + pyi) * WIMG + tx * TILE + pxi;
        out[3 * pix + 0] = rr;
        out[3 * pix + 1] = gg;
        out[3 * pix + 2] = bb;
    }
}

extern "C" void kernel_launch(void* const* d_in, const int* in_sizes, int n_in,
                              void* d_out, int out_size) {
    (void)in_sizes; (void)n_in; (void)out_size;
    const float* means = (const float*)d_in[0];
    const float* rots  = (const float*)d_in[1];
    const float* lsc   = (const float*)d_in[2];
    const float* cols  = (const float*)d_in[3];
    float* out = (float*)d_out;

    bin_prep_kernel<<<NTILES, 256>>>(means, rots, lsc, cols);
    render_kernel<<<NTILES * 2, 256>>>(out);
}

// round 8
// speedup vs baseline: 1.5817x; 1.5817x over previous
#include <cuda_runtime.h>

#define NG     2048
#define WIMG   128
#define KTOP   10
#define TILE   8
#define TPD    16
#define NTILES 256
#define SPLIT  4
#define CAP    1024

// ---- scratch (__device__ globals; no allocations) ----
__device__ float4 d_P4[NG];            // (-mean_x, -mean_y, a', b')  [-0.5*log2e folded]
__device__ float  d_PC[NG];            // c'
__device__ float4 d_C4[NG];            // (r, g, b, 0)
__device__ int    d_list[NTILES * NG]; // per-tile gaussian index lists (ascending g)
__device__ int    d_cnt[NTILES];

// One block per tile. Bitmask cull + warp-scan ordered compaction (verified R6).
// Blocks 0..7 also compute per-gaussian quadratic params (one g per thread).
__global__ void __launch_bounds__(256) bin_prep_kernel(
    const float* __restrict__ means, const float* __restrict__ rots,
    const float* __restrict__ lsc,   const float* __restrict__ cols) {
    __shared__ unsigned s_hw[64];   // hit bits: word w bit b <-> gaussian 32w+b
    __shared__ int      s_gb[32];   // exclusive base per 64-gaussian group

    const int tile = blockIdx.x;
    const int t    = threadIdx.x;
    const float x0 = (float)((tile & 15) * TILE) + 0.5f;
    const float y0 = (float)((tile >> 4) * TILE) + 0.5f;
    const float x1 = x0 + 7.0f, y1 = y0 + 7.0f;

    // ---- param writes (blocks 0..7 only; g = blockIdx.x*256 + t) ----
    if (blockIdx.x < 8) {
        int g = blockIdx.x * 256 + t;
        float th = rots[g];
        float ct = cosf(th), st = sinf(th);
        float ivx = expf(-2.0f * lsc[2*g + 0]);
        float ivy = expf(-2.0f * lsc[2*g + 1]);
        float a = ct*ct*ivx + st*st*ivy;
        float c = st*st*ivx + ct*ct*ivy;
        float b = ct*st*(ivx - ivy);
        const float L = 1.4426950408889634f;   // log2(e)
        // alpha = 2^(a' dx^2 + b' dx dy + c' dy^2)
        d_P4[g] = make_float4(-means[2*g + 0], -means[2*g + 1], -0.5f*L*a, -L*b);
        d_PC[g] = -0.5f * L * c;
        d_C4[g] = make_float4(cols[3*g + 0], cols[3*g + 1], cols[3*g + 2], 0.0f);
    }

    // ---- hit tests: thread t covers gaussians [8t, 8t+8), vectorized ----
    const float4* m4 = (const float4*)means;  // 2 gaussians per float4
    const float4* l4 = (const float4*)lsc;
    unsigned mask = 0;
#pragma unroll
    for (int j = 0; j < 4; j++) {
        float4 mm = m4[4*t + j];
        float4 ll = l4[4*t + j];
        // cull at 4.5*sigma_max: alpha < 4e-5 outside (error bound << 1e-3)
        float r = 4.5f * __expf(fmaxf(ll.x, ll.y));
        float cdx = fmaxf(fmaxf(x0 - mm.x, mm.x - x1), 0.0f);
        float cdy = fmaxf(fmaxf(y0 - mm.y, mm.y - y1), 0.0f);
        if (cdx*cdx + cdy*cdy <= r*r) mask |= 1u << (2*j);
        r = 4.5f * __expf(fmaxf(ll.z, ll.w));
        cdx = fmaxf(fmaxf(x0 - mm.z, mm.z - x1), 0.0f);
        cdy = fmaxf(fmaxf(y0 - mm.w, mm.w - y1), 0.0f);
        if (cdx*cdx + cdy*cdy <= r*r) mask |= 1u << (2*j + 1);
    }
    ((unsigned char*)s_hw)[t] = (unsigned char)mask;  // byte t&3 of word t>>2
    __syncthreads();

    // ---- warp 0: inclusive shfl-scan of popcounts over 64-gaussian groups ----
    if (t < 32) {
        int c = __popc(s_hw[2*t]) + __popc(s_hw[2*t + 1]);
        int inc = c;
#pragma unroll
        for (int d = 1; d < 32; d <<= 1) {
            int n = __shfl_up_sync(0xffffffffu, inc, d);
            if (t >= d) inc += n;
        }
        s_gb[t] = inc - c;
        if (t == 31) d_cnt[tile] = inc;
    }
    __syncthreads();

    // ---- ordered scatter (ascending g) ----
    {
        int grp = t >> 3;                       // 64-gaussian group
        unsigned w0 = s_hw[2*grp], w1 = s_hw[2*grp + 1];
        int bidx = t & 7;                       // byte index within group
        int pre;
        if (bidx < 4) pre = __popc(w0 & ((1u << (8*bidx)) - 1u));
        else          pre = __popc(w0) + __popc(w1 & ((1u << (8*(bidx-4))) - 1u));
        int pos = s_gb[grp] + pre;
        int* lst = d_list + tile * NG;
#pragma unroll
        for (int j = 0; j < 8; j++)
            if (mask & (1u << j)) lst[pos++] = 8*t + j;
    }
}

__device__ __forceinline__ float ex2f(float x) {
    float y;
    asm("ex2.approx.ftz.f32 %0, %1;" : "=f"(y) : "f"(x));
    return y;
}

// One block per tile: 64 px x SPLIT(4) = 256 threads, grid 256. Params staged
// in shared once. u32 alpha bits + separate index registers (verified R3/R5
// ordering: ascending-g scan + strict '>' + ascending-split merge == top_k).
__global__ void __launch_bounds__(256) render_kernel(float* __restrict__ out) {
    __shared__ float4   s_p4[CAP];
    __shared__ float2   s_pcg[CAP];                  // (c', g as int-bits)
    __shared__ unsigned s_al[64][SPLIT * KTOP + 1];  // stride 41 -> conflict-free
    __shared__ int      s_ix[64][SPLIT * KTOP + 1];

    const int tile = blockIdx.x;
    const int tid  = threadIdx.x;
    const int pit  = tid & 63;      // pixel in tile; warp = 32 adjacent pixels
    const int sp   = tid >> 6;      // split id 0..3
    const int tx = tile & (TPD-1), ty = tile >> 4;
    const int pxi = pit & (TILE-1), pyi = pit >> 3;
    const float px = (float)(tx * TILE + pxi) + 0.5f;
    const float py = (float)(ty * TILE + pyi) + 0.5f;

    const int len = d_cnt[tile];
    const int* __restrict__ lst = d_list + tile * NG;

    // stage list params into shared (once per tile)
    const int lim = len < CAP ? len : CAP;
    for (int i = tid; i < lim; i += 256) {
        int g = lst[i];
        s_p4[i]  = d_P4[g];
        s_pcg[i] = make_float2(d_PC[g], __int_as_float(g));
    }
    __syncthreads();

    const int chunk = (len + SPLIT - 1) / SPLIT;
    const int s = sp * chunk;
    const int e = min(s + chunk, len);

    unsigned al[KTOP]; int ix[KTOP];
#pragma unroll
    for (int k = 0; k < KTOP; k++) { al[k] = 0u; ix[k] = 0; }

    // smem range (no per-iter branch)
    const int e1 = min(e, CAP);
#pragma unroll 2
    for (int i = s; i < e1; i++) {
        float4 p   = s_p4[i];
        float2 pcg = s_pcg[i];
        float dx = px + p.x;
        float dy = py + p.y;
        float t1 = fmaf(p.w, dy, p.z * dx);
        float q  = fmaf(dx, t1, (pcg.x * dy) * dy);
        float alpha = ex2f(q);
        unsigned abits = __float_as_uint(alpha);   // alpha>0 -> monotone as u32
        if (abits > al[KTOP - 1]) {
            unsigned va = abits; int vi = __float_as_int(pcg.y);
#pragma unroll
            for (int k = 0; k < KTOP; k++) {
                bool tk = va > al[k];
                unsigned na = tk ? al[k] : va;
                int      ni = tk ? ix[k] : vi;
                al[k] = tk ? va : al[k];
                ix[k] = tk ? vi : ix[k];
                va = na; vi = ni;
            }
        }
    }
    // global fallback range (len > CAP only; never expected, kept for safety)
    for (int i = (s > CAP ? s : CAP); i < e; i++) {
        int g = __ldg(lst + i);
        float4 p  = d_P4[g];
        float  cc = d_PC[g];
        float dx = px + p.x;
        float dy = py + p.y;
        float t1 = fmaf(p.w, dy, p.z * dx);
        float q  = fmaf(dx, t1, (cc * dy) * dy);
        float alpha = ex2f(q);
        unsigned abits = __float_as_uint(alpha);
        if (abits > al[KTOP - 1]) {
            unsigned va = abits; int vi = g;
#pragma unroll
            for (int k = 0; k < KTOP; k++) {
                bool tk = va > al[k];
                unsigned na = tk ? al[k] : va;
                int      ni = tk ? ix[k] : vi;
                al[k] = tk ? va : al[k];
                ix[k] = tk ? vi : ix[k];
                va = na; vi = ni;
            }
        }
    }

#pragma unroll
    for (int k = 0; k < KTOP; k++) {
        s_al[pit][sp * KTOP + k] = al[k];
        s_ix[pit][sp * KTOP + k] = ix[k];
    }
    __syncthreads();

    if (tid < 64) {
        int h0 = 0, h1 = 0, h2 = 0, h3 = 0;
        float T = 1.0f, rr = 0.0f, gg = 0.0f, bb = 0.0f;
#pragma unroll
        for (int k = 0; k < KTOP; k++) {
            unsigned best = s_al[tid][0*KTOP + h0]; int bs = 0;
            unsigned v;
            v = s_al[tid][1*KTOP + h1]; if (v > best) { best = v; bs = 1; }
            v = s_al[tid][2*KTOP + h2]; if (v > best) { best = v; bs = 2; }
            v = s_al[tid][3*KTOP + h3]; if (v > best) { best = v; bs = 3; }
            int bi = s_ix[tid][bs * KTOP + ((bs==0)?h0:(bs==1)?h1:(bs==2)?h2:h3)];
            h0 += (bs == 0); h1 += (bs == 1); h2 += (bs == 2); h3 += (bs == 3);

            float alpha = __uint_as_float(best);
            float4 col = d_C4[bi];
            float wgt = alpha * T;
            rr = fmaf(wgt, col.x, rr);
            gg = fmaf(wgt, col.y, gg);
            bb = fmaf(wgt, col.z, bb);
            T *= (1.0f - alpha);
        }
        int pix = (ty * TILE + (tid >> 3)) * WIMG + tx * TILE + (tid & 7);
        out[3 * pix + 0] = rr;
        out[3 * pix + 1] = gg;
        out[3 * pix + 2] = bb;
    }
}

extern "C" void kernel_launch(void* const* d_in, const int* in_sizes, int n_in,
                              void* d_out, int out_size) {
    (void)in_sizes; (void)n_in; (void)out_size;
    const float* means = (const float*)d_in[0];
    const float* rots  = (const float*)d_in[1];
    const float* lsc   = (const float*)d_in[2];
    const float* cols  = (const float*)d_in[3];
    float* out = (float*)d_out;

    bin_prep_kernel<<<NTILES, 256>>>(means, rots, lsc, cols);
    render_kernel<<<NTILES, 256>>>(out);
}